// round 13
// baseline (speedup 1.0000x reference)
#include <cuda_runtime.h>
#include <cuda_fp16.h>
#include <math.h>
#include <stdint.h>

#define NN    8192
#define FIN   256
#define FOUT  128
#define JS    2
#define JPB   (NN / JS)          // 4096
#define NT    (JPB / 128)        // 32
#define PBUF  32768              // 128x128 fp16, swizzled

__device__ float    g_Xp[NN * FOUT];
__device__ __half   g_XphT[(size_t)FOUT * NN];
__device__ float    g_asrc[NN], g_adst[NN];
__device__ uint32_t g_Fh2[NN / 2], g_Hh2[NN / 2];
__device__ float    g_max[1];
__device__ uint32_t g_bits[(size_t)JS * NN * 128];   // 8 MB: [js][i][word]
__device__ float    g_part[(size_t)JS * NN * FOUT];
__device__ float    g_lpart[JS * NN];

__device__ __forceinline__ uint32_t smem_u32(const void* p) {
    uint32_t a;
    asm("{ .reg .u64 t; cvta.to.shared.u64 t, %1; cvt.u32.u64 %0, t; }" : "=r"(a) : "l"(p));
    return a;
}
#define LDSM4(r, addr)                                                           \
    asm volatile("ldmatrix.sync.aligned.m8n8.x4.shared.b16 {%0,%1,%2,%3}, [%4];" \
        : "=r"((r)[0]), "=r"((r)[1]), "=r"((r)[2]), "=r"((r)[3]) : "r"(addr))
#define MMA16816(d, a, b0, b1)                                                   \
    asm volatile("mma.sync.aligned.m16n8k16.row.col.f32.f16.f16.f32 "            \
        "{%0,%1,%2,%3},{%4,%5,%6,%7},{%8,%9},{%0,%1,%2,%3};"                     \
        : "+f"((d)[0]), "+f"((d)[1]), "+f"((d)[2]), "+f"((d)[3])                 \
        : "r"((a)[0]), "r"((a)[1]), "r"((a)[2]), "r"((a)[3]), "r"(b0), "r"(b1))
#define CP_ASYNC16(dst, src) \
    asm volatile("cp.async.cg.shared.global [%0], [%1], 16;" :: "r"(dst), "l"(src))
#define CP_COMMIT() asm volatile("cp.async.commit_group;" ::: "memory")
#define CP_WAIT0()  asm volatile("cp.async.wait_group 0;" ::: "memory")
#define CP_WAIT1()  asm volatile("cp.async.wait_group 1;" ::: "memory")
#define BAR_SYNC(id, cnt) asm volatile("bar.sync %0, %1;" :: "r"(id), "r"(cnt) : "memory")
#define MBARRIER_INIT(mb, cnt) \
    asm volatile("mbarrier.init.shared.b64 [%0], %1;" :: "r"(mb), "r"(cnt) : "memory")
#define MBARRIER_EXPECT_TX(mb, bytes) \
    asm volatile("mbarrier.arrive.expect_tx.shared.b64 _, [%0], %1;" :: "r"(mb), "r"(bytes) : "memory")
#define MBARRIER_WAIT_PARITY(mb, ph) do {                                            \
    uint32_t _m = (mb), _p = (ph), _d;                                               \
    asm volatile("{\n\t.reg .pred p;\n\t"                                            \
        "mbarrier.try_wait.parity.acquire.cta.shared::cta.b64 p, [%1], %2;\n\t"      \
        "selp.b32 %0, 1, 0, p;\n\t}" : "=r"(_d) : "r"(_m), "r"(_p) : "memory");      \
    if (!_d) {                                                                       \
        asm volatile("{\n\t.reg .pred P1;\n\t"                                       \
            "WL%=:\n\t"                                                              \
            "mbarrier.try_wait.parity.acquire.cta.shared::cta.b64 P1, [%0], %1, 0x989680;\n\t" \
            "@P1 bra.uni WD%=;\n\t bra.uni WL%=;\n\t WD%=:\n\t}"                     \
            :: "r"(_m), "r"(_p) : "memory");                                         \
    }                                                                                \
} while (0)
#define BULK_G2S(dst, src, bytes, mb)                                                 \
    asm volatile("cp.async.bulk.shared::cluster.global.mbarrier::complete_tx::bytes " \
        "[%0], [%1], %2, [%3];" :: "r"(dst), "l"(src), "r"(bytes), "r"(mb) : "memory")

// ================= Kernel 0: bit-pack adjacency (one row per CTA) =================
__global__ void __launch_bounds__(256) prepack_kernel(const int* __restrict__ adj) {
    __shared__ __align__(128) int srow[NN];          // 32 KB
    __shared__ __align__(8) unsigned long long smb;
    const int i = blockIdx.x;
    const int t = threadIdx.x;
    const uint32_t mb = smem_u32(&smb);
    if (t == 0) MBARRIER_INIT(mb, 1);
    __syncthreads();
    if (t == 0) {
        MBARRIER_EXPECT_TX(mb, 32768);
        BULK_G2S(smem_u32(srow), (const void*)(adj + (size_t)i * NN), 32768, mb);
    }
    MBARRIER_WAIT_PARITY(mb, 0);
    const int4* s4 = (const int4*)srow;
    uint32_t wbits = 0;
#pragma unroll
    for (int k = 0; k < 8; k++) {
        const int q = (k + t) & 7;
        const int4 v = s4[t * 8 + q];
        uint32_t nib = (v.x != 0 ? 1u : 0u) | (v.y != 0 ? 2u : 0u)
                     | (v.z != 0 ? 4u : 0u) | (v.w != 0 ? 8u : 0u);
        wbits |= nib << (q * 4);
    }
    const int js = t >> 7;
    const int lw = t & 127;
    if ((i >> 12) == js && ((i >> 5) & 127) == lw) wbits |= 1u << (i & 31);
    g_bits[(size_t)js * (NN * 128) + (size_t)i * 128 + lw] = wbits;
}

// ================= Kernel 1: Xp = X W^T + b (+fp16 transpose) =================
__global__ void gemm_xp_kernel(const float* __restrict__ X,
                               const float* __restrict__ W,
                               const float* __restrict__ b) {
    __shared__ float Xs[64][17];
    __shared__ float Ws[64][17];
    const int tx = threadIdx.x, ty = threadIdx.y;
    const int tid = ty * 16 + tx;
    const int row0 = blockIdx.y * 64, col0 = blockIdx.x * 64;
    const int lr = tid >> 2, lk = (tid & 3) * 4;
    float acc[4][4];
#pragma unroll
    for (int i = 0; i < 4; i++)
#pragma unroll
        for (int j = 0; j < 4; j++) acc[i][j] = 0.f;
    for (int kt = 0; kt < FIN; kt += 16) {
        float4 xv = *reinterpret_cast<const float4*>(&X[(row0 + lr) * FIN + kt + lk]);
        Xs[lr][lk + 0] = xv.x; Xs[lr][lk + 1] = xv.y;
        Xs[lr][lk + 2] = xv.z; Xs[lr][lk + 3] = xv.w;
        float4 wv = *reinterpret_cast<const float4*>(&W[(col0 + lr) * FIN + kt + lk]);
        Ws[lr][lk + 0] = wv.x; Ws[lr][lk + 1] = wv.y;
        Ws[lr][lk + 2] = wv.z; Ws[lr][lk + 3] = wv.w;
        __syncthreads();
#pragma unroll
        for (int k = 0; k < 16; ++k) {
            float a[4], w[4];
#pragma unroll
            for (int i = 0; i < 4; i++) a[i] = Xs[ty * 4 + i][k];
#pragma unroll
            for (int j = 0; j < 4; j++) w[j] = Ws[tx * 4 + j][k];
#pragma unroll
            for (int i = 0; i < 4; i++)
#pragma unroll
                for (int j = 0; j < 4; j++) acc[i][j] += a[i] * w[j];
        }
        __syncthreads();
    }
#pragma unroll
    for (int i = 0; i < 4; i++) {
        const int row = row0 + ty * 4 + i;
#pragma unroll
        for (int j = 0; j < 4; j++) {
            const int f = col0 + tx * 4 + j;
            const float v = acc[i][j] + b[f];
            g_Xp[row * FOUT + f] = v;
            g_XphT[(size_t)f * NN + row] = __float2half(v);
        }
    }
}

// ================= Kernel 2: projections =================
__global__ void proj_kernel(const float* __restrict__ S) {
    int gw   = (blockIdx.x * blockDim.x + threadIdx.x) >> 5;
    int lane = threadIdx.x & 31;
    if (gw >= NN) return;
    const float4 x  = *((const float4*)(g_Xp + gw * FOUT) + lane);
    const float4 s1 = *((const float4*)(S) + lane);
    const float4 s2 = *((const float4*)(S + FOUT) + lane);
    float ss = x.x * s1.x + x.y * s1.y + x.z * s1.z + x.w * s1.w;
    float sd = x.x * s2.x + x.y * s2.y + x.z * s2.z + x.w * s2.w;
#pragma unroll
    for (int o = 16; o > 0; o >>= 1) {
        ss += __shfl_down_sync(0xffffffffu, ss, o);
        sd += __shfl_down_sync(0xffffffffu, sd, o);
    }
    if (lane == 0) { g_asrc[gw] = ss; g_adst[gw] = sd; }
}

// ================= Kernel 3: global max of a_dst =================
__global__ void maxred_kernel() {
    __shared__ float red[32];
    const int t = threadIdx.x;  // 1024
    float m = -3e38f;
    for (int i = t; i < NN; i += 1024) m = fmaxf(m, g_adst[i]);
#pragma unroll
    for (int o = 16; o > 0; o >>= 1) m = fmaxf(m, __shfl_down_sync(0xffffffffu, m, o));
    if ((t & 31) == 0) red[t >> 5] = m;
    __syncthreads();
    if (t < 32) {
        float v = red[t];
#pragma unroll
        for (int o = 16; o > 0; o >>= 1) v = fmaxf(v, __shfl_down_sync(0xffffffffu, v, o));
        if (t == 0) g_max[0] = v;
    }
}

// ========= Kernel 3b: packed half2 factors =========
__global__ void prep_kernel() {
    const int j2 = blockIdx.x * 256 + threadIdx.x;
    if (j2 >= NN / 2) return;
    const float mx = g_max[0];
    const float a0 = g_adst[2 * j2]     - mx;
    const float a1 = g_adst[2 * j2 + 1] - mx;
    __half2 F = __floats2half2_rn(__expf(a0), __expf(a1));
    __half2 H = __floats2half2_rn(__expf(0.01f * a0), __expf(0.01f * a1));
    g_Fh2[j2] = *(uint32_t*)&F;
    g_Hh2[j2] = *(uint32_t*)&H;
}

// ===== Kernel 4: warp-specialized attention over smem-resident bits =====
// warps 0-7 consumers (MMA 64x32 tiles), warps 8-15 producers (P build from bits)
#define SM_BITS 0
#define SM_P    65536
#define SM_B    131072
#define SM_C1   196608
#define SM_C2   197120
#define SM_MB   197632
#define SMEM_ATTN 197664

__device__ __forceinline__ void mma_tile_c(uint32_t pb, uint32_t bb, int wm, int wn,
                                           int lane, float acc[4][4][4], float accL[4][4]) {
    const uint32_t ONE2 = 0x3C003C00u;
    const int xa = lane & 7;
    const uint32_t rowA = pb + (uint32_t)(wm * 64 + (lane & 15)) * 256;
    const int ca = lane >> 4;
    const uint32_t rowB = bb + (uint32_t)(wn * 32 + (lane & 7) + ((lane >> 4) << 3)) * 256;
    const int cb = (lane >> 3) & 1;
#pragma unroll
    for (int ks = 0; ks < 8; ks++) {
        uint32_t bfr[2][4];
#pragma unroll
        for (int nt = 0; nt < 2; nt++) {
            const uint32_t addr = rowB + nt * 4096 + (((2 * ks + cb) ^ xa) << 4);
            LDSM4(bfr[nt], addr);
        }
#pragma unroll
        for (int mt = 0; mt < 4; mt++) {
            uint32_t a[4];
            const uint32_t addr = rowA + mt * 4096 + (((2 * ks + ca) ^ xa) << 4);
            LDSM4(a, addr);
#pragma unroll
            for (int nt = 0; nt < 2; nt++) {
                MMA16816(acc[mt][nt * 2 + 0], a, bfr[nt][0], bfr[nt][1]);
                MMA16816(acc[mt][nt * 2 + 1], a, bfr[nt][2], bfr[nt][3]);
            }
            if (wn == 0) MMA16816(accL[mt], a, ONE2, ONE2);
        }
    }
}

__global__ void __launch_bounds__(512, 1)
attn_kernel() {
    extern __shared__ char smem[];
    const uint32_t su = smem_u32(smem);
    float* sC1 = (float*)(smem + SM_C1);
    float* sC2 = (float*)(smem + SM_C2);
    const uint32_t* sbits = (const uint32_t*)(smem + SM_BITS);
    const uint32_t mb = su + SM_MB;

    const int tid  = threadIdx.x;
    const int w    = tid >> 5;
    const int lane = tid & 31;
    const int i0    = blockIdx.x * 128;
    const int js    = blockIdx.y;
    const int jbase = js * JPB;

    if (tid < 128) {
        const float as = __ldg(&g_asrc[i0 + tid]);
        const float mx = __ldg(&g_max[0]);
        const float s  = as + mx;
        const float m  = fmaxf(s, 0.01f * s);
        sC1[tid] = __expf(as + mx - m);
        sC2[tid] = __expf(0.01f * (as + mx) - m);
    }
    if (tid == 0) MBARRIER_INIT(mb, 1);
    __syncthreads();

    // bits: 64KB contiguous, 2 bulk ops
    if (tid == 0) MBARRIER_EXPECT_TX(mb, 65536);
    if (tid < 2)
        BULK_G2S(su + SM_BITS + tid * 32768,
                 (const void*)(g_bits + (size_t)js * (NN * 128) + (size_t)i0 * 128 + tid * 8192),
                 32768, mb);

    if (w < 8) {
        // ======================= CONSUMERS (warps 0-7) =======================
        const int wm = w & 1;          // 64-row slice
        const int wn = w >> 1;         // 32-col slice
        const int bf  = tid >> 1;
        const int bfx = bf & 7;
        const __half* bsrc = g_XphT + (size_t)bf * NN + jbase;
        const uint32_t bdst_row = su + SM_B + (uint32_t)bf * 256;
#define ISSUE_B(t)                                                               \
        do {                                                                     \
            const uint32_t _bb = bdst_row + ((t) & 1) * PBUF;                    \
            _Pragma("unroll")                                                    \
            for (int _it = 0; _it < 8; _it++) {                                  \
                const int _c = (tid & 1) * 8 + _it;                              \
                CP_ASYNC16(_bb + ((_c ^ bfx) << 4),                              \
                           (const char*)(bsrc + (t) * 128 + _c * 8));            \
            }                                                                    \
            CP_COMMIT();                                                         \
        } while (0)
        ISSUE_B(0);

        float acc[4][4][4];
#pragma unroll
        for (int mt = 0; mt < 4; mt++)
#pragma unroll
            for (int nf = 0; nf < 4; nf++)
#pragma unroll
                for (int q = 0; q < 4; q++) acc[mt][nf][q] = 0.f;
        float accL[4][4];
#pragma unroll
        for (int mt = 0; mt < 4; mt++)
#pragma unroll
            for (int q = 0; q < 4; q++) accL[mt][q] = 0.f;

#pragma unroll 1
        for (int t = 0; t < NT; t++) {
            if (t > 0) {
                const int s = (t - 1) & 1;
                mma_tile_c(su + SM_P + s * PBUF, su + SM_B + s * PBUF,
                           wm, wn, lane, acc, accL);
            }
            BAR_SYNC(5, 256);           // consumers: MMA(t-1) done (B reuse safe)
            if (t + 1 < NT) { ISSUE_B(t + 1); CP_WAIT1(); }
            else           { CP_WAIT0(); }
            __syncthreads();            // P(t)/B(t) published for iteration t+1
        }
        {
            const int s = (NT - 1) & 1;
            mma_tile_c(su + SM_P + s * PBUF, su + SM_B + s * PBUF,
                       wm, wn, lane, acc, accL);
        }
        // ---- epilogue ----
        {
            float* dst = g_part + ((size_t)js * NN + i0) * FOUT;
            const int rbase = wm * 64 + (lane >> 2);
            const int cbase = wn * 32 + (lane & 3) * 2;
#pragma unroll
            for (int mt = 0; mt < 4; mt++) {
#pragma unroll
                for (int nf = 0; nf < 4; nf++) {
                    const int r = rbase + mt * 16;
                    const int c = cbase + nf * 8;
                    *(float2*)(dst + (size_t)r * FOUT + c) =
                        make_float2(acc[mt][nf][0], acc[mt][nf][1]);
                    *(float2*)(dst + (size_t)(r + 8) * FOUT + c) =
                        make_float2(acc[mt][nf][2], acc[mt][nf][3]);
                }
            }
            if (wn == 0 && (lane & 3) == 0) {
#pragma unroll
                for (int mt = 0; mt < 4; mt++) {
                    const int r = wm * 64 + mt * 16 + (lane >> 2);
                    g_lpart[js * NN + i0 + r]     = accL[mt][0];
                    g_lpart[js * NN + i0 + r + 8] = accL[mt][2];
                }
            }
        }
    } else {
        // ======================= PRODUCERS (warps 8-15) =======================
        const int p  = tid - 256;      // 0..255
        const int rq = p >> 4;         // 16 groups of 8 rows
        const int jq = p & 15;         // 16 groups of 8 j
        const int bsh = (jq & 3) * 8;

        uint32_t C1h[8], C2h[8];
#pragma unroll
        for (int r = 0; r < 8; r++) {
            const int row = rq * 8 + r;
            __half2 h1 = __half2half2(__float2half(sC1[row]));
            __half2 h2 = __half2half2(__float2half(sC2[row]));
            C1h[r] = *(uint32_t*)&h1; C2h[r] = *(uint32_t*)&h2;
        }
        MBARRIER_WAIT_PARITY(mb, 0);   // bits resident

#pragma unroll 1
        for (int t = 0; t < NT; t++) {
            const int s = t & 1;
            uint32_t Fh[4], Hh[4];
            {
                const int p2 = (jbase + t * 128) / 2 + jq * 4;
                *(uint4*)Fh = __ldg((const uint4*)(g_Fh2 + p2));
                *(uint4*)Hh = __ldg((const uint4*)(g_Hh2 + p2));
            }
            char* Pb = smem + SM_P + s * PBUF;
            const int wofs = t * 4 + (jq >> 2);
#pragma unroll
            for (int r = 0; r < 8; r++) {
                const int row = rq * 8 + r;
                const uint32_t b = (sbits[row * 128 + wofs] >> bsh) & 0xFFu;
                uint32_t st[4];
#pragma unroll
                for (int pr = 0; pr < 4; pr++) {
                    const uint32_t two = (b >> (2 * pr)) & 3u;
                    const uint32_t msk = ((two & 1u) ? 0x0000FFFFu : 0u)
                                       | ((two & 2u) ? 0xFFFF0000u : 0u);
                    const __half2 s1 = __hmul2(*(__half2*)&C1h[r], *(__half2*)&Fh[pr]);
                    const __half2 s2 = __hmul2(*(__half2*)&C2h[r], *(__half2*)&Hh[pr]);
                    const __half2 sm = __hmax2(s1, s2);
                    st[pr] = (*(uint32_t*)&sm) & msk;
                }
                *(uint4*)(Pb + row * 256 + ((jq ^ (row & 7)) << 4)) = *(uint4*)st;
            }
            __syncthreads();            // publish P(t); pairs with consumer sync
        }
    }
}

// ================= Kernel 5: combine + sigmoid =================
__global__ void combine_kernel(float* __restrict__ out) {
    const int gid = blockIdx.x * 256 + threadIdx.x;
    const int i = gid >> 5;
    const int c = gid & 31;
    float4 s = make_float4(0.f, 0.f, 0.f, 0.f);
    float L = 0.f;
#pragma unroll
    for (int js = 0; js < JS; js++) {
        const float4 a = *(const float4*)(g_part + ((size_t)js * NN + i) * FOUT + c * 4);
        s.x += a.x; s.y += a.y; s.z += a.z; s.w += a.w;
        L += g_lpart[js * NN + i];
    }
    const float inv = 1.f / L;
    float4 o;
    o.x = 1.f / (1.f + __expf(-s.x * inv));
    o.y = 1.f / (1.f + __expf(-s.y * inv));
    o.z = 1.f / (1.f + __expf(-s.z * inv));
    o.w = 1.f / (1.f + __expf(-s.w * inv));
    *(float4*)(out + (size_t)i * FOUT + c * 4) = o;
}

extern "C" void kernel_launch(void* const* d_in, const int* in_sizes, int n_in,
                              void* d_out, int out_size) {
    const float* X   = (const float*)d_in[0];
    const int*   adj = (const int*)  d_in[1];
    const float* W   = (const float*)d_in[2];
    const float* b   = (const float*)d_in[3];
    const float* S   = (const float*)d_in[4];
    float* out = (float*)d_out;

    prepack_kernel<<<NN, 256>>>(adj);
    gemm_xp_kernel<<<dim3(FOUT / 64, NN / 64), dim3(16, 16)>>>(X, W, b);
    proj_kernel<<<(NN * 32) / 256, 256>>>(S);
    maxred_kernel<<<1, 1024>>>();
    prep_kernel<<<NN / 512, 256>>>();

    cudaFuncSetAttribute(attn_kernel, cudaFuncAttributeMaxDynamicSharedMemorySize, SMEM_ATTN);
    attn_kernel<<<dim3(NN / 128, JS), 512, SMEM_ATTN>>>();
    combine_kernel<<<(NN * 32) / 256, 256>>>(out);
}

// round 14
// speedup vs baseline: 1.4075x; 1.4075x over previous
#include <cuda_runtime.h>
#include <cuda_fp16.h>
#include <math.h>
#include <stdint.h>

#define NN    8192
#define FIN   256
#define FOUT  128
#define JS    2
#define JPB   (NN / JS)          // 4096
#define NT    (JPB / 128)        // 32 tiles -> 64 half-tiles
#define PBUF  32768              // 128x128 fp16, swizzled
#define AHALF 32768              // 64 rows x 512B adj half-tile

__device__ float    g_Xp[NN * FOUT];
__device__ __half   g_XphT[(size_t)FOUT * NN];
__device__ float    g_asrc[NN], g_adst[NN];
__device__ uint32_t g_Fh2[NN / 2], g_Hh2[NN / 2];
__device__ unsigned g_maxu;
__device__ float    g_max[1];
__device__ float    g_part[(size_t)JS * NN * FOUT];
__device__ float    g_lpart[JS * NN];

__device__ __forceinline__ uint32_t smem_u32(const void* p) {
    uint32_t a;
    asm("{ .reg .u64 t; cvta.to.shared.u64 t, %1; cvt.u32.u64 %0, t; }" : "=r"(a) : "l"(p));
    return a;
}
__device__ __forceinline__ unsigned fenc(float f) {
    unsigned u = __float_as_uint(f);
    return (u & 0x80000000u) ? ~u : (u | 0x80000000u);
}
__device__ __forceinline__ float fdec(unsigned u) {
    return (u & 0x80000000u) ? __uint_as_float(u & 0x7FFFFFFFu) : __uint_as_float(~u);
}
#define LDSM4(r, addr)                                                           \
    asm volatile("ldmatrix.sync.aligned.m8n8.x4.shared.b16 {%0,%1,%2,%3}, [%4];" \
        : "=r"((r)[0]), "=r"((r)[1]), "=r"((r)[2]), "=r"((r)[3]) : "r"(addr))
#define MMA16816(d, a, b0, b1)                                                   \
    asm volatile("mma.sync.aligned.m16n8k16.row.col.f32.f16.f16.f32 "            \
        "{%0,%1,%2,%3},{%4,%5,%6,%7},{%8,%9},{%0,%1,%2,%3};"                     \
        : "+f"((d)[0]), "+f"((d)[1]), "+f"((d)[2]), "+f"((d)[3])                 \
        : "r"((a)[0]), "r"((a)[1]), "r"((a)[2]), "r"((a)[3]), "r"(b0), "r"(b1))
#define CP_ASYNC16(dst, src) \
    asm volatile("cp.async.cg.shared.global [%0], [%1], 16;" :: "r"(dst), "l"(src))
#define CP_COMMIT() asm volatile("cp.async.commit_group;" ::: "memory")
#define CP_WAIT0()  asm volatile("cp.async.wait_group 0;" ::: "memory")
#define MBARRIER_INIT(mb, cnt) \
    asm volatile("mbarrier.init.shared.b64 [%0], %1;" :: "r"(mb), "r"(cnt) : "memory")
#define MBARRIER_EXPECT_TX(mb, bytes) \
    asm volatile("mbarrier.arrive.expect_tx.shared.b64 _, [%0], %1;" :: "r"(mb), "r"(bytes) : "memory")
#define MBARRIER_WAIT_PARITY(mb, ph) do {                                            \
    uint32_t _m = (mb), _p = (ph), _d;                                               \
    asm volatile("{\n\t.reg .pred p;\n\t"                                            \
        "mbarrier.try_wait.parity.acquire.cta.shared::cta.b64 p, [%1], %2;\n\t"      \
        "selp.b32 %0, 1, 0, p;\n\t}" : "=r"(_d) : "r"(_m), "r"(_p) : "memory");      \
    if (!_d) {                                                                       \
        asm volatile("{\n\t.reg .pred P1;\n\t"                                       \
            "WL%=:\n\t"                                                              \
            "mbarrier.try_wait.parity.acquire.cta.shared::cta.b64 P1, [%0], %1, 0x989680;\n\t" \
            "@P1 bra.uni WD%=;\n\t bra.uni WL%=;\n\t WD%=:\n\t}"                     \
            :: "r"(_m), "r"(_p) : "memory");                                         \
    }                                                                                \
} while (0)
#define BULK_G2S(dst, src, bytes, mb)                                                 \
    asm volatile("cp.async.bulk.shared::cluster.global.mbarrier::complete_tx::bytes " \
        "[%0], [%1], %2, [%3];" :: "r"(dst), "l"(src), "r"(bytes), "r"(mb) : "memory")

// ====== Kernel 1: Xp = X W^T + b ; coalesced fp16 transpose via smem staging ======
__global__ void gemm_xp_kernel(const float* __restrict__ X,
                               const float* __restrict__ W,
                               const float* __restrict__ b) {
    __shared__ float  Xs[64][17];
    __shared__ float  Ws[64][17];
    __shared__ __half sXT[64][72];     // [f_local][row_local], padded
    const int tx = threadIdx.x, ty = threadIdx.y;
    const int tid = ty * 16 + tx;
    const int row0 = blockIdx.y * 64, col0 = blockIdx.x * 64;
    const int lr = tid >> 2, lk = (tid & 3) * 4;

    if (blockIdx.x == 0 && blockIdx.y == 0 && tid == 0) g_maxu = 0u;  // reset for proj

    float acc[4][4];
#pragma unroll
    for (int i = 0; i < 4; i++)
#pragma unroll
        for (int j = 0; j < 4; j++) acc[i][j] = 0.f;
    for (int kt = 0; kt < FIN; kt += 16) {
        float4 xv = *reinterpret_cast<const float4*>(&X[(row0 + lr) * FIN + kt + lk]);
        Xs[lr][lk + 0] = xv.x; Xs[lr][lk + 1] = xv.y;
        Xs[lr][lk + 2] = xv.z; Xs[lr][lk + 3] = xv.w;
        float4 wv = *reinterpret_cast<const float4*>(&W[(col0 + lr) * FIN + kt + lk]);
        Ws[lr][lk + 0] = wv.x; Ws[lr][lk + 1] = wv.y;
        Ws[lr][lk + 2] = wv.z; Ws[lr][lk + 3] = wv.w;
        __syncthreads();
#pragma unroll
        for (int k = 0; k < 16; ++k) {
            float a[4], w[4];
#pragma unroll
            for (int i = 0; i < 4; i++) a[i] = Xs[ty * 4 + i][k];
#pragma unroll
            for (int j = 0; j < 4; j++) w[j] = Ws[tx * 4 + j][k];
#pragma unroll
            for (int i = 0; i < 4; i++)
#pragma unroll
                for (int j = 0; j < 4; j++) acc[i][j] += a[i] * w[j];
        }
        __syncthreads();
    }
#pragma unroll
    for (int i = 0; i < 4; i++) {
        const int row = row0 + ty * 4 + i;
#pragma unroll
        for (int j = 0; j < 4; j++) {
            const int f = col0 + tx * 4 + j;
            const float v = acc[i][j] + b[f];
            g_Xp[row * FOUT + f] = v;
            sXT[tx * 4 + j][ty * 4 + i] = __float2half(v);
        }
    }
    __syncthreads();
    // coalesced transpose store: each thread writes 32B of one f-row
    {
        const int fl = tid >> 2;
        const int c  = tid & 3;
        const uint4* src = (const uint4*)(&sXT[fl][c * 16]);
        uint4* dst = (uint4*)(g_XphT + (size_t)(col0 + fl) * NN + row0 + c * 16);
        dst[0] = src[0];
        dst[1] = src[1];
    }
}

// ====== Kernel 2: projections + fused global max (atomic, encoded) ======
__global__ void proj_kernel(const float* __restrict__ S) {
    __shared__ float wmax[8];
    int gw   = (blockIdx.x * blockDim.x + threadIdx.x) >> 5;
    int lane = threadIdx.x & 31;
    const float4 x  = *((const float4*)(g_Xp + gw * FOUT) + lane);
    const float4 s1 = *((const float4*)(S) + lane);
    const float4 s2 = *((const float4*)(S + FOUT) + lane);
    float ss = x.x * s1.x + x.y * s1.y + x.z * s1.z + x.w * s1.w;
    float sd = x.x * s2.x + x.y * s2.y + x.z * s2.z + x.w * s2.w;
#pragma unroll
    for (int o = 16; o > 0; o >>= 1) {
        ss += __shfl_down_sync(0xffffffffu, ss, o);
        sd += __shfl_down_sync(0xffffffffu, sd, o);
    }
    if (lane == 0) {
        g_asrc[gw] = ss; g_adst[gw] = sd;
        wmax[(threadIdx.x >> 5)] = sd;
    }
    __syncthreads();
    if (threadIdx.x == 0) {
        float m = wmax[0];
#pragma unroll
        for (int k = 1; k < 8; k++) m = fmaxf(m, wmax[k]);
        atomicMax(&g_maxu, fenc(m));
    }
}

// ========= Kernel 3: packed half2 factors (decodes max, republishes float) =========
__global__ void prep_kernel() {
    const int j2 = blockIdx.x * 256 + threadIdx.x;
    if (j2 >= NN / 2) return;
    const float mx = fdec(g_maxu);
    if (j2 == 0) g_max[0] = mx;
    const float a0 = g_adst[2 * j2]     - mx;
    const float a1 = g_adst[2 * j2 + 1] - mx;
    __half2 F = __floats2half2_rn(__expf(a0), __expf(a1));
    __half2 H = __floats2half2_rn(__expf(0.01f * a0), __expf(0.01f * a1));
    g_Fh2[j2] = *(uint32_t*)&F;
    g_Hh2[j2] = *(uint32_t*)&H;
}

// ===== Kernel 4: 512-thread attention (R9 structure, unchanged) =====
#define SM_ADJ  0
#define SM_P    98304
#define SM_B    163840
#define SM_C1   229376
#define SM_C2   229888
#define SM_MB   230400
#define SMEM_ATTN 230432

__global__ void __launch_bounds__(512, 1)
attn_kernel(const int* __restrict__ adj) {
    extern __shared__ char smem[];
    const uint32_t su = smem_u32(smem);
    float* sC1 = (float*)(smem + SM_C1);
    float* sC2 = (float*)(smem + SM_C2);
    const uint32_t adj_u = su + SM_ADJ;
    const uint32_t mbb   = su + SM_MB;

    const int tid  = threadIdx.x;
    const int w    = tid >> 5;
    const int lane = tid & 31;
    const int rq   = tid >> 4;       // 32 row-groups of 4
    const int jq   = tid & 15;       // 16 j-groups of 8
    const int wm   = w & 3, wn = w >> 2;   // MMA warp tile 32x32
    const int i0    = blockIdx.x * 128;
    const int js    = blockIdx.y;
    const int jbase = js * JPB;
    const bool hasdiag = ((i0 >> 12) == js);
    const int tstar = (i0 - jbase) >> 7;

    if (tid < 128) {
        const float as = __ldg(&g_asrc[i0 + tid]);
        const float mx = __ldg(&g_max[0]);
        const float s  = as + mx;
        const float m  = fmaxf(s, 0.01f * s);
        sC1[tid] = __expf(as + mx - m);
        sC2[tid] = __expf(0.01f * (as + mx) - m);
    }
    if (tid == 0) {
        MBARRIER_INIT(mbb + 0, 1);
        MBARRIER_INIT(mbb + 8, 1);
        MBARRIER_INIT(mbb + 16, 1);
    }
    __syncthreads();

    // initial adj halves 0,1,2
    if (tid < 192) {
        const int h = tid >> 6;
        const int r = tid & 63;
        if (r == 0) MBARRIER_EXPECT_TX(mbb + h * 8, AHALF);
        BULK_G2S(adj_u + (uint32_t)h * AHALF + (uint32_t)r * 512,
                 (const void*)(adj + (size_t)(i0 + (h & 1) * 64 + r) * NN
                               + jbase + (h >> 1) * 128),
                 512, mbb + h * 8);
    }

    // B issue: 512 threads, 4 chunks each
    const int bf  = tid >> 2;
    const int bfx = bf & 7;
    const __half* bsrc = g_XphT + (size_t)bf * NN + jbase;
    const uint32_t bdst_row = su + SM_B + (uint32_t)bf * 256;
#define ISSUE_B(t)                                                               \
    do {                                                                         \
        const uint32_t _bb = bdst_row + ((t) & 1) * PBUF;                        \
        _Pragma("unroll")                                                        \
        for (int _it = 0; _it < 4; _it++) {                                      \
            const int _c = (tid & 3) * 4 + _it;                                  \
            CP_ASYNC16(_bb + ((_c ^ bfx) << 4),                                  \
                       (const char*)(bsrc + (t) * 128 + _c * 8));                \
        }                                                                        \
        CP_COMMIT();                                                             \
    } while (0)
    ISSUE_B(0);

    float C1f[4], C2f[4];
    uint32_t C1h[4], C2h[4];
#pragma unroll
    for (int r = 0; r < 4; r++) {
        const int row = rq * 4 + r;
        C1f[r] = sC1[row]; C2f[r] = sC2[row];
        __half2 h1 = __half2half2(__float2half(C1f[r]));
        __half2 h2 = __half2half2(__float2half(C2f[r]));
        C1h[r] = *(uint32_t*)&h1; C2h[r] = *(uint32_t*)&h2;
    }
    float acc[2][4][4];
#pragma unroll
    for (int mt = 0; mt < 2; mt++)
#pragma unroll
        for (int nf = 0; nf < 4; nf++)
#pragma unroll
            for (int q = 0; q < 4; q++) acc[mt][nf][q] = 0.f;
    float accL[2][4];
#pragma unroll
    for (int mt = 0; mt < 2; mt++)
#pragma unroll
        for (int q = 0; q < 4; q++) accL[mt][q] = 0.f;
    const uint32_t ONE2 = 0x3C003C00u;

    const int myhalf = rq >> 4;

#pragma unroll 1
    for (int t = 0; t < NT; t++) {
        const int s = t & 1;
        uint32_t Fh[4], Hh[4];
        {
            const int p2 = (jbase + t * 128) / 2 + jq * 4;
            *(uint4*)Fh = __ldg((const uint4*)(g_Fh2 + p2));
            *(uint4*)Hh = __ldg((const uint4*)(g_Hh2 + p2));
        }
        const int h = 2 * t + myhalf;
        const int slot = h % 3;
        MBARRIER_WAIT_PARITY(mbb + slot * 8, (h / 3) & 1);
        // ---- build P(t) ----
        {
            char* Pb = smem + SM_P + s * PBUF;
            const int* As = (const int*)(smem + SM_ADJ + slot * AHALF);
#pragma unroll
            for (int r = 0; r < 4; r++) {
                const int row = rq * 4 + r;
                const int4 a0 = *(const int4*)(As + (row & 63) * 128 + jq * 8);
                const int4 a1 = *(const int4*)(As + (row & 63) * 128 + jq * 8 + 4);
                const int mk[8] = { a0.x, a0.y, a0.z, a0.w, a1.x, a1.y, a1.z, a1.w };
                uint32_t st[4];
#pragma unroll
                for (int pr = 0; pr < 4; pr++) {
                    const uint32_t msk = ((uint32_t)(-mk[2 * pr]) & 0xFFFFu)
                                       | ((uint32_t)(-mk[2 * pr + 1]) & 0xFFFF0000u);
                    const __half2 s1 = __hmul2(*(__half2*)&C1h[r], *(__half2*)&Fh[pr]);
                    const __half2 s2 = __hmul2(*(__half2*)&C2h[r], *(__half2*)&Hh[pr]);
                    const __half2 sm = __hmax2(s1, s2);
                    st[pr] = (*(uint32_t*)&sm) & msk;
                }
                *(uint4*)(Pb + row * 256 + ((jq ^ (row & 7)) << 4)) = *(uint4*)st;
            }
            if (hasdiag && t == tstar && jq == (rq >> 1)) {
#pragma unroll
                for (int r = 0; r < 4; r++) {
                    const int row = rq * 4 + r;
                    const int cl = row & 7;
                    const __half* fp = (const __half*)&Fh[cl >> 1];
                    const __half* hp = (const __half*)&Hh[cl >> 1];
                    const float pv = fmaxf(C1f[r] * __half2float(fp[cl & 1]),
                                           C2f[r] * __half2float(hp[cl & 1]));
                    *(__half*)(Pb + row * 256 + ((jq ^ cl) << 4) + (cl & 7) * 2) =
                        __float2half(pv);
                }
            }
        }
        CP_WAIT0();
        __syncthreads();
        // refill adj halves 2t+3, 2t+4 ; issue B(t+1)
        {
            const int nh = 2 * t + 3 + (tid >> 6);
            if (tid < 128 && nh < 2 * NT) {
                const int r = tid & 63;
                const int ns = nh % 3;
                if (r == 0) MBARRIER_EXPECT_TX(mbb + ns * 8, AHALF);
                BULK_G2S(adj_u + (uint32_t)ns * AHALF + (uint32_t)r * 512,
                         (const void*)(adj + (size_t)(i0 + (nh & 1) * 64 + r) * NN
                                       + jbase + (nh >> 1) * 128),
                         512, mbb + ns * 8);
            }
            if (t + 1 < NT) ISSUE_B(t + 1);
        }
        // ---- MMA(t): warp tile 32x32 ----
        {
            const uint32_t pb = su + SM_P + s * PBUF;
            const uint32_t bb = su + SM_B + s * PBUF;
            const int xa = lane & 7;
            const uint32_t rowA = pb + (uint32_t)(wm * 32 + (lane & 15)) * 256;
            const int ca = lane >> 4;
            const uint32_t rowB = bb + (uint32_t)(wn * 32 + (lane & 7) + ((lane >> 4) << 3)) * 256;
            const int cb = (lane >> 3) & 1;
#pragma unroll
            for (int ks = 0; ks < 8; ks++) {
                uint32_t a[2][4];
#pragma unroll
                for (int mt = 0; mt < 2; mt++) {
                    const uint32_t addr = rowA + mt * 4096 + (((2 * ks + ca) ^ xa) << 4);
                    LDSM4(a[mt], addr);
                }
#pragma unroll
                for (int nt = 0; nt < 2; nt++) {
                    uint32_t bfr[4];
                    const uint32_t addr = rowB + nt * 4096 + (((2 * ks + cb) ^ xa) << 4);
                    LDSM4(bfr, addr);
#pragma unroll
                    for (int mt = 0; mt < 2; mt++) {
                        MMA16816(acc[mt][nt * 2 + 0], a[mt], bfr[0], bfr[1]);
                        MMA16816(acc[mt][nt * 2 + 1], a[mt], bfr[2], bfr[3]);
                    }
                }
                if (wn == 0) {
#pragma unroll
                    for (int mt = 0; mt < 2; mt++)
                        MMA16816(accL[mt], a[mt], ONE2, ONE2);
                }
            }
        }
    }

    // ---- epilogue ----
    {
        float* dst = g_part + ((size_t)js * NN + i0) * FOUT;
        const int rbase = wm * 32 + (lane >> 2);
        const int cbase = wn * 32 + (lane & 3) * 2;
#pragma unroll
        for (int mt = 0; mt < 2; mt++) {
#pragma unroll
            for (int nf = 0; nf < 4; nf++) {
                const int r = rbase + mt * 16;
                const int c = cbase + nf * 8;
                *(float2*)(dst + (size_t)r * FOUT + c) =
                    make_float2(acc[mt][nf][0], acc[mt][nf][1]);
                *(float2*)(dst + (size_t)(r + 8) * FOUT + c) =
                    make_float2(acc[mt][nf][2], acc[mt][nf][3]);
            }
        }
        if (wn == 0 && (lane & 3) == 0) {
#pragma unroll
            for (int mt = 0; mt < 2; mt++) {
                const int r = wm * 32 + mt * 16 + (lane >> 2);
                g_lpart[js * NN + i0 + r]     = accL[mt][0];
                g_lpart[js * NN + i0 + r + 8] = accL[mt][2];
            }
        }
    }
}

// ================= Kernel 5: combine + sigmoid =================
__global__ void combine_kernel(float* __restrict__ out) {
    const int gid = blockIdx.x * 256 + threadIdx.x;
    const int i = gid >> 5;
    const int c = gid & 31;
    float4 s = make_float4(0.f, 0.f, 0.f, 0.f);
    float L = 0.f;
#pragma unroll
    for (int js = 0; js < JS; js++) {
        const float4 a = *(const float4*)(g_part + ((size_t)js * NN + i) * FOUT + c * 4);
        s.x += a.x; s.y += a.y; s.z += a.z; s.w += a.w;
        L += g_lpart[js * NN + i];
    }
    const float inv = 1.f / L;
    float4 o;
    o.x = 1.f / (1.f + __expf(-s.x * inv));
    o.y = 1.f / (1.f + __expf(-s.y * inv));
    o.z = 1.f / (1.f + __expf(-s.z * inv));
    o.w = 1.f / (1.f + __expf(-s.w * inv));
    *(float4*)(out + (size_t)i * FOUT + c * 4) = o;
}

extern "C" void kernel_launch(void* const* d_in, const int* in_sizes, int n_in,
                              void* d_out, int out_size) {
    const float* X   = (const float*)d_in[0];
    const int*   adj = (const int*)  d_in[1];
    const float* W   = (const float*)d_in[2];
    const float* b   = (const float*)d_in[3];
    const float* S   = (const float*)d_in[4];
    float* out = (float*)d_out;

    gemm_xp_kernel<<<dim3(FOUT / 64, NN / 64), dim3(16, 16)>>>(X, W, b);
    proj_kernel<<<(NN * 32) / 256, 256>>>(S);
    prep_kernel<<<NN / 512, 256>>>();

    cudaFuncSetAttribute(attn_kernel, cudaFuncAttributeMaxDynamicSharedMemorySize, SMEM_ATTN);
    attn_kernel<<<dim3(NN / 128, JS), 512, SMEM_ATTN>>>(adj);
    combine_kernel<<<(NN * 32) / 256, 256>>>(out);
}